// round 14
// baseline (speedup 1.0000x reference)
#include <cuda_runtime.h>
#include <cuda_bf16.h>
#include <cstdint>

// RaySampler: N=32 cameras, resolution=512 (M=262144 rays/cam).
// Output (fp32): [ray_origins (N,M,3)][ray_dirs (N,M,3)] = 201.3 MB writes.
//
// R12 was L1-wavefront bound (L1=65.5%): 3 broadcast LDG.128 per thread for
// the camera table added ~27% extra L1tex traffic on top of the stores.
// R13 tried __constant__ but passed the __device__ symbol directly as the
// memcpy SRC pointer (host shadow address -> garbage). Fixed here with
// cudaGetSymbolAddress. Hot kernel: LDC (const port, zero L1tex) + FMA +
// rsqrt + 2 coalesced streaming STG.128 per thread.

static constexpr int RES = 512;
static constexpr int M_RAYS = RES * RES;                  // 262144
static constexpr int QUADS_PER_CAM = M_RAYS / 4;          // 65536
static constexpr float INV_RES = 1.0f / (float)RES;
static constexpr int MAXN = 128;

// Per-camera: [3n+0]=(Px,Py,Pz,ox) [3n+1]=(Qx,Qy,Qz,oy) [3n+2]=(Rx,Ry,Rz,oz)
__device__   float4 g_camtab[MAXN * 3];
__constant__ float4 c_camtab[MAXN * 3];

__global__ void precompute_kernel(const float* __restrict__ cam,
                                  const float* __restrict__ intr, int N)
{
    const int n = blockIdx.x * blockDim.x + threadIdx.x;
    if (n >= N) return;

    const float* Mn = cam + n * 16;
    const float3 A = make_float3(Mn[0], Mn[4], Mn[8]);     // rot col 0
    const float3 B = make_float3(Mn[1], Mn[5], Mn[9]);     // rot col 1
    const float3 C = make_float3(-Mn[2], -Mn[6], -Mn[10]); // -rot col 2
    const float ox = Mn[3], oy = Mn[7], oz = Mn[11];

    const float* In = intr + n * 9;
    const float fx = In[0], sk = In[1], cx = In[2];
    const float fy = In[4], cy = In[5];
    const float ifx = 1.0f / fx;
    const float ify = 1.0f / fy;

    // w = P*x_cam + Q*y_cam + R  (unnormalized direction, affine in pixel)
    const float s  = sk * ify * ifx;
    const float rx = (cy * sk * ify - cx) * ifx;
    const float ry = cy * ify;

    float3 P, Q, R;
    P.x = A.x * ifx;                 P.y = A.y * ifx;                 P.z = A.z * ifx;
    Q.x = -(A.x * s + B.x * ify);    Q.y = -(A.y * s + B.y * ify);    Q.z = -(A.z * s + B.z * ify);
    R.x = A.x * rx + B.x * ry + C.x; R.y = A.y * rx + B.y * ry + C.y; R.z = A.z * rx + B.z * ry + C.z;

    // Fold pixel scaling: x_cam=(col+0.5)/RES, y_cam=(row+0.5)/RES
    float3 Pp = make_float3(P.x * INV_RES, P.y * INV_RES, P.z * INV_RES);
    float3 Qp = make_float3(Q.x * INV_RES, Q.y * INV_RES, Q.z * INV_RES);
    float3 Rp = make_float3(R.x + 0.5f * (Pp.x + Qp.x),
                            R.y + 0.5f * (Pp.y + Qp.y),
                            R.z + 0.5f * (Pp.z + Qp.z));

    g_camtab[3 * n + 0] = make_float4(Pp.x, Pp.y, Pp.z, ox);
    g_camtab[3 * n + 1] = make_float4(Qp.x, Qp.y, Qp.z, oy);
    g_camtab[3 * n + 2] = make_float4(Rp.x, Rp.y, Rp.z, oz);
}

__global__ void __launch_bounds__(256)
ray_sampler_kernel(float4* __restrict__ out_org,
                   float4* __restrict__ out_dir)
{
    const unsigned g = blockIdx.x * blockDim.x + threadIdx.x;  // float4 slot
    const unsigned q = g / 3u;                                 // ray quad
    const int p = (int)(g - q * 3u);                           // window phase

    const int n  = (int)(q >> 16);                             // quad/65536
    const int m0 = (int)(q & (QUADS_PER_CAM - 1)) << 2;        // first ray
    const float rowf = (float)(m0 >> 9);
    const float colf = (float)((m0 & (RES - 1)) + p);          // ray A col

    // Warp-uniform constant loads (constant port, zero L1tex traffic).
    const float4 Pv = c_camtab[3 * n + 0];
    const float4 Qv = c_camtab[3 * n + 1];
    const float4 Rv = c_camtab[3 * n + 2];

    // base = Q*row + R  (shared by both rays)
    const float bx = fmaf(Qv.x, rowf, Rv.x);
    const float by = fmaf(Qv.y, rowf, Rv.y);
    const float bz = fmaf(Qv.z, rowf, Rv.z);

    // ray A (col), ray B (col+1) = A + P
    float ax = fmaf(Pv.x, colf, bx);
    float ay = fmaf(Pv.y, colf, by);
    float az = fmaf(Pv.z, colf, bz);
    float ex = ax + Pv.x;
    float ey = ay + Pv.y;
    float ez = az + Pv.z;

    const float ia = rsqrtf(fmaxf(fmaf(ax, ax, fmaf(ay, ay, az * az)), 1e-24f));
    const float ib = rsqrtf(fmaxf(fmaf(ex, ex, fmaf(ey, ey, ez * ez)), 1e-24f));
    ax *= ia; ay *= ia; az *= ia;
    ex *= ib; ey *= ib; ez *= ib;

    float4 dv, ov;
    if (p == 0) {
        dv = make_float4(ax, ay, az, ex);
        ov = make_float4(Pv.w, Qv.w, Rv.w, Pv.w);
    } else if (p == 1) {
        dv = make_float4(ay, az, ex, ey);
        ov = make_float4(Qv.w, Rv.w, Pv.w, Qv.w);
    } else {
        dv = make_float4(az, ex, ey, ez);
        ov = make_float4(Rv.w, Pv.w, Qv.w, Rv.w);
    }

    __stcs(&out_dir[g], dv);    // streaming: write-once, evict-first
    __stcs(&out_org[g], ov);
}

extern "C" void kernel_launch(void* const* d_in, const int* in_sizes, int n_in,
                              void* d_out, int out_size)
{
    const float* cam  = (const float*)d_in[0];   // (N,4,4) fp32
    const float* intr = (const float*)d_in[1];   // (N,3,3) fp32
    const int N = in_sizes[0] / 16;              // 32

    precompute_kernel<<<(N + 31) / 32, 32>>>(cam, intr, N);

    // Real device address of the __device__ table (symbol->address lookup;
    // non-stream API, safe under graph capture), then D2D memcpy node into
    // the constant bank.
    void* src = nullptr;
    cudaGetSymbolAddress(&src, g_camtab);
    cudaMemcpyToSymbolAsync(c_camtab, src,
                            (size_t)N * 3 * sizeof(float4), 0,
                            cudaMemcpyDeviceToDevice);

    const size_t T4 = (size_t)N * M_RAYS * 3u / 4u;   // 6,291,456 float4s
    float4* out_org = (float4*)d_out;
    float4* out_dir = (float4*)d_out + T4;

    dim3 block(256);
    dim3 grid((unsigned)(T4 / 256));             // 24576 blocks, exact
    ray_sampler_kernel<<<grid, block>>>(out_org, out_dir);
}

// round 15
// speedup vs baseline: 1.1179x; 1.1179x over previous
#include <cuda_runtime.h>
#include <cuda_bf16.h>
#include <cstdint>

// RaySampler: N=32 cameras, resolution=512 (M=262144 rays/cam).
// Output (fp32): [ray_origins (N,M,3)][ray_dirs (N,M,3)] = 201.3 MB writes.
//
// R14 lesson: the hot kernel hit 28.3us but precompute-kernel + memcpy graph
// nodes cost ~6.6us/replay. This round is ONE fused kernel:
//   - camera index is block-uniform (blockIdx.y); thread 0 computes the
//     per-camera affine params {P,Q,R,origin} (dir = P*col + Q*row + R,
//     then normalize) into smem from raw cam/intr (L2-broadcast, ~100B/blk).
//   - 256 threads x 2 coalesced float4 slots per thread (block = 512 slots,
//     196608 slots/cam / 512 = 384 blocks/cam exactly).
//   - streaming STG.128 stores, rsqrt normalize, zero global loads in the
//     per-ray path.

static constexpr int RES = 512;
static constexpr int M_RAYS = RES * RES;                    // 262144
static constexpr int SLOTS_PER_CAM = M_RAYS * 3 / 4;        // 196608 float4s
static constexpr int BLOCKS_PER_CAM = SLOTS_PER_CAM / 512;  // 384
static constexpr float INV_RES = 1.0f / (float)RES;

__global__ void __launch_bounds__(256)
ray_sampler_kernel(const float* __restrict__ cam,     // (N,4,4)
                   const float* __restrict__ intr,    // (N,3,3)
                   float4* __restrict__ out_org,
                   float4* __restrict__ out_dir)
{
    __shared__ float4 sT[3];   // [0]=(P,ox) [1]=(Q,oy) [2]=(R,oz)

    const int n = blockIdx.y;

    if (threadIdx.x == 0) {
        const float* Mn = cam + n * 16;
        const float3 A = make_float3(Mn[0], Mn[4], Mn[8]);     // rot col 0
        const float3 B = make_float3(Mn[1], Mn[5], Mn[9]);     // rot col 1
        const float3 C = make_float3(-Mn[2], -Mn[6], -Mn[10]); // -rot col 2
        const float ox = Mn[3], oy = Mn[7], oz = Mn[11];

        const float* In = intr + n * 9;
        const float fx = In[0], sk = In[1], cx = In[2];
        const float fy = In[4], cy = In[5];
        const float ifx = 1.0f / fx;
        const float ify = 1.0f / fy;

        // w = P*x_cam + Q*y_cam + R (unnormalized dir, affine in pixel).
        const float s  = sk * ify * ifx;
        const float rx = (cy * sk * ify - cx) * ifx;
        const float ry = cy * ify;

        float3 P, Q, R;
        P.x = A.x * ifx;                 P.y = A.y * ifx;                 P.z = A.z * ifx;
        Q.x = -(A.x * s + B.x * ify);    Q.y = -(A.y * s + B.y * ify);    Q.z = -(A.z * s + B.z * ify);
        R.x = A.x * rx + B.x * ry + C.x; R.y = A.y * rx + B.y * ry + C.y; R.z = A.z * rx + B.z * ry + C.z;

        // Fold pixel scaling x_cam=(col+0.5)/RES, y_cam=(row+0.5)/RES.
        float3 Pp = make_float3(P.x * INV_RES, P.y * INV_RES, P.z * INV_RES);
        float3 Qp = make_float3(Q.x * INV_RES, Q.y * INV_RES, Q.z * INV_RES);
        float3 Rp = make_float3(R.x + 0.5f * (Pp.x + Qp.x),
                                R.y + 0.5f * (Pp.y + Qp.y),
                                R.z + 0.5f * (Pp.z + Qp.z));

        sT[0] = make_float4(Pp.x, Pp.y, Pp.z, ox);
        sT[1] = make_float4(Qp.x, Qp.y, Qp.z, oy);
        sT[2] = make_float4(Rp.x, Rp.y, Rp.z, oz);
    }
    __syncthreads();

    const float4 Pv = sT[0];
    const float4 Qv = sT[1];
    const float4 Rv = sT[2];

    const unsigned l0 = blockIdx.x * 512u + threadIdx.x;   // slot within camera
    const size_t gbase = (size_t)n * SLOTS_PER_CAM;

#pragma unroll
    for (int k = 0; k < 2; ++k) {
        const unsigned l = l0 + (unsigned)k * 256u;
        const unsigned q = l / 3u;                  // ray quad within camera
        const int p = (int)(l - q * 3u);            // window phase

        const float rowf = (float)(q >> 7);                       // m0>>9
        const float colf = (float)((int)((q & 127u) << 2) + p);   // ray A col

        // base = Q*row + R (shared by both rays of this slot)
        const float bx = fmaf(Qv.x, rowf, Rv.x);
        const float by = fmaf(Qv.y, rowf, Rv.y);
        const float bz = fmaf(Qv.z, rowf, Rv.z);

        // ray A (col), ray B (col+1) = A + P
        float ax = fmaf(Pv.x, colf, bx);
        float ay = fmaf(Pv.y, colf, by);
        float az = fmaf(Pv.z, colf, bz);
        float ex = ax + Pv.x;
        float ey = ay + Pv.y;
        float ez = az + Pv.z;

        const float ia = rsqrtf(fmaxf(fmaf(ax, ax, fmaf(ay, ay, az * az)), 1e-24f));
        const float ib = rsqrtf(fmaxf(fmaf(ex, ex, fmaf(ey, ey, ez * ez)), 1e-24f));
        ax *= ia; ay *= ia; az *= ia;
        ex *= ib; ey *= ib; ez *= ib;

        float4 dv, ov;
        if (p == 0) {
            dv = make_float4(ax, ay, az, ex);
            ov = make_float4(Pv.w, Qv.w, Rv.w, Pv.w);
        } else if (p == 1) {
            dv = make_float4(ay, az, ex, ey);
            ov = make_float4(Qv.w, Rv.w, Pv.w, Qv.w);
        } else {
            dv = make_float4(az, ex, ey, ez);
            ov = make_float4(Rv.w, Pv.w, Qv.w, Rv.w);
        }

        __stcs(&out_dir[gbase + l], dv);   // coalesced streaming stores
        __stcs(&out_org[gbase + l], ov);
    }
}

extern "C" void kernel_launch(void* const* d_in, const int* in_sizes, int n_in,
                              void* d_out, int out_size)
{
    const float* cam  = (const float*)d_in[0];   // (N,4,4) fp32
    const float* intr = (const float*)d_in[1];   // (N,3,3) fp32
    const int N = in_sizes[0] / 16;              // 32

    float4* out_org = (float4*)d_out;
    float4* out_dir = (float4*)d_out + (size_t)N * SLOTS_PER_CAM;

    dim3 block(256);
    dim3 grid(BLOCKS_PER_CAM, N);                // (384, 32) = 12288 blocks
    ray_sampler_kernel<<<grid, block>>>(cam, intr, out_org, out_dir);
}